// round 13
// baseline (speedup 1.0000x reference)
#include <cuda_runtime.h>
#include <cuda_bf16.h>
#include <cuda_fp16.h>
#include <cstdint>

// ---------------------------------------------------------------------------
// Net_9560597201379 : SNN encoder/decoder.  (round-11 structure)
//   G1+enc1 fused: fp32 scalar-FMA GEMM (exact sequential-k chain).
//   G2: HMMA bf16 3-way-split W -> cur2 ; enc2 scan standalone.
//   G3+dec1 fused: HMMA bf16 3-way-split W, m3 scan in regs -> s3 (fp16).
//   G4 fused: single-pass fp16 HMMA + m4 scan (reset provably 0) + spk
//     zero-fill spread across k-groups.  NEW: __launch_bounds__(256,3) to
//     lift occupancy 2->3 CTAs/SM (profile showed tensor 30%, occ 21.9% --
//     latency-bound; reg spills land in epilogue-only state).
// ---------------------------------------------------------------------------

__device__ __nv_bfloat16  g_s1  [8*1024*256];
__device__ float          g_cur2[8*1024*128];
__device__ __nv_bfloat16  g_spk [8*1024*128];
__device__ __half         g_s3  [8*8192*256];
__device__ __nv_bfloat16  g_w2hi[128*256], g_w2mi[128*256], g_w2lo[128*256];
__device__ __nv_bfloat16  g_w3hi[256*128], g_w3mi[256*128], g_w3lo[256*128];
__device__ __half         g_w4h [512*256];

// ===================== helpers =============================================

__device__ __forceinline__ uint32_t smem_u32(const void* p) {
    uint32_t a;
    asm("{ .reg .u64 t; cvta.to.shared.u64 t, %1; cvt.u32.u64 %0, t; }"
        : "=r"(a) : "l"(p));
    return a;
}

__device__ __forceinline__ void cp16(uint32_t s, const void* g) {
    asm volatile("cp.async.cg.shared.global [%0], [%1], 16;" :: "r"(s), "l"(g));
}
__device__ __forceinline__ void cp_commit() {
    asm volatile("cp.async.commit_group;");
}
template <int N> __device__ __forceinline__ void cp_wait() {
    asm volatile("cp.async.wait_group %0;" :: "n"(N));
}

__device__ __forceinline__ void mma16816(float* d, const uint32_t* a,
                                         uint32_t b0, uint32_t b1) {
    asm volatile(
        "mma.sync.aligned.m16n8k16.row.col.f32.bf16.bf16.f32 "
        "{%0,%1,%2,%3}, {%4,%5,%6,%7}, {%8,%9}, {%0,%1,%2,%3};"
        : "+f"(d[0]), "+f"(d[1]), "+f"(d[2]), "+f"(d[3])
        : "r"(a[0]), "r"(a[1]), "r"(a[2]), "r"(a[3]), "r"(b0), "r"(b1));
}

__device__ __forceinline__ void mma16816h(float* d, const uint32_t* a,
                                          uint32_t b0, uint32_t b1) {
    asm volatile(
        "mma.sync.aligned.m16n8k16.row.col.f32.f16.f16.f32 "
        "{%0,%1,%2,%3}, {%4,%5,%6,%7}, {%8,%9}, {%0,%1,%2,%3};"
        : "+f"(d[0]), "+f"(d[1]), "+f"(d[2]), "+f"(d[3])
        : "r"(a[0]), "r"(a[1]), "r"(a[2]), "r"(a[3]), "r"(b0), "r"(b1));
}

__device__ __forceinline__ void ldsm4(uint32_t* r, uint32_t a) {
    asm volatile("ldmatrix.sync.aligned.m8n8.x4.shared.b16 {%0,%1,%2,%3}, [%4];"
                 : "=r"(r[0]), "=r"(r[1]), "=r"(r[2]), "=r"(r[3]) : "r"(a));
}

// spike pair -> packed bf16x2 bits (1.0f bf16 = 0x3F80)
__device__ __forceinline__ uint32_t spike_pack(float m0, float m1, float th) {
    uint32_t lo = (m0 - th > 0.0f) ? 0x3F80u : 0u;
    uint32_t hi = (m1 - th > 0.0f) ? 0x3F80u : 0u;
    return lo | (hi << 16);
}
// spike pair -> packed fp16x2 bits (1.0f fp16 = 0x3C00)
__device__ __forceinline__ uint32_t spike_pack_h(float m0, float m1) {
    uint32_t lo = (m0 - 1.0f > 0.0f) ? 0x3C00u : 0u;
    uint32_t hi = (m1 - 1.0f > 0.0f) ? 0x3C00u : 0u;
    return lo | (hi << 16);
}

static const int ROWB = 144;              // smem row: 64 b16 data + pad
static const int MATB = 128 * ROWB;       // 18432 B per 128x64 tile

// ===================== G1 + enc1 fused =====================================
// grid = (8,16), block 256.  Exact chain: fma.rn ascending k, +bias last.

__global__ __launch_bounds__(256) void g1_enc1(
    const float* __restrict__ A, const float* __restrict__ B,
    const float* __restrict__ bias, __nv_bfloat16* __restrict__ S1)
{
    __shared__ float As[16][68];   // [k][row]
    __shared__ float Bs[16][36];   // [k][col]

    const int tid = threadIdx.x;
    const int bx = blockIdx.x, by = blockIdx.y;
    const int arow = tid >> 2, akq = (tid & 3) * 4;
    const int brow = tid >> 3, bkq = (tid & 7) * 2;
    const int tr = (tid >> 4) * 4, tc = (tid & 15) * 2;

    const float* Ab = A + (size_t)(by * 64) * 512;
    const float* Bb = B + (size_t)(bx * 32) * 512;

    float4 ar = *reinterpret_cast<const float4*>(Ab + arow * 512 + akq);
    float2 br = *reinterpret_cast<const float2*>(Bb + brow * 512 + bkq);

    float acc[4][2];
#pragma unroll
    for (int i = 0; i < 4; i++) { acc[i][0] = 0.0f; acc[i][1] = 0.0f; }

    for (int c = 0; c < 32; c++) {
        As[akq + 0][arow] = ar.x;
        As[akq + 1][arow] = ar.y;
        As[akq + 2][arow] = ar.z;
        As[akq + 3][arow] = ar.w;
        Bs[bkq + 0][brow] = br.x;
        Bs[bkq + 1][brow] = br.y;
        __syncthreads();
        if (c + 1 < 32) {
            ar = *reinterpret_cast<const float4*>(Ab + arow * 512 + (c + 1) * 16 + akq);
            br = *reinterpret_cast<const float2*>(Bb + brow * 512 + (c + 1) * 16 + bkq);
        }
#pragma unroll
        for (int kk = 0; kk < 16; kk++) {
            float4 av = *reinterpret_cast<const float4*>(&As[kk][tr]);
            float b0 = Bs[kk][tc], b1 = Bs[kk][tc + 1];
            acc[0][0] = fmaf(av.x, b0, acc[0][0]);
            acc[0][1] = fmaf(av.x, b1, acc[0][1]);
            acc[1][0] = fmaf(av.y, b0, acc[1][0]);
            acc[1][1] = fmaf(av.y, b1, acc[1][1]);
            acc[2][0] = fmaf(av.z, b0, acc[2][0]);
            acc[2][1] = fmaf(av.z, b1, acc[2][1]);
            acc[3][0] = fmaf(av.w, b0, acc[3][0]);
            acc[3][1] = fmaf(av.w, b1, acc[3][1]);
        }
        __syncthreads();
    }

    const int col = bx * 32 + tc;
    const float bv0 = bias[col], bv1 = bias[col + 1];
#pragma unroll
    for (int i = 0; i < 4; i++) {
        const int row = by * 64 + tr + i;
        float c0 = acc[i][0] + bv0;
        float c1 = acc[i][1] + bv1;
        float m0 = 0.0f, m1 = 0.0f;
        uint32_t* dst = reinterpret_cast<uint32_t*>(S1 + (size_t)row * 256 + col);
#pragma unroll
        for (int k = 0; k < 8; k++) {
            float r0 = (m0 - 1.0f > 0.0f) ? 1.0f : 0.0f;
            float r1 = (m1 - 1.0f > 0.0f) ? 1.0f : 0.0f;
            m0 = 0.9f * m0 + c0 - r0;
            m1 = 0.9f * m1 + c1 - r1;
            dst[k * 131072] = spike_pack(m0, m1, 1.0f);
        }
    }
}

// ===================== generic HMMA GEMM (G2 / G3+dec1) ====================
// bf16, 3-way-split weights; bitwise-identical to the proven round-8 version.

template <int NB, bool DEC1>
__global__ __launch_bounds__(256, 2) void mma_gemm_split(
    const __nv_bfloat16* __restrict__ A,
    const __nv_bfloat16* __restrict__ B0,
    const __nv_bfloat16* __restrict__ B1,
    const __nv_bfloat16* __restrict__ B2,
    const float* __restrict__ bias,
    float* __restrict__ C, __half* __restrict__ S3,
    int M, int N, int K)
{
    constexpr int STAGEB = (1 + NB) * MATB;
    extern __shared__ char sm[];
    const uint32_t sb = smem_u32(sm);
    const int tid = threadIdx.x, wid = tid >> 5, lane = tid & 31;
    const int bx = blockIdx.x, by = blockIdx.y;
    const int g = lane >> 2, tig = lane & 3;
    const int wm = (wid >> 2) * 64, wn = (wid & 3) * 32;

    const __nv_bfloat16* Ab = A + (size_t)(by * 128) * K;
    const __nv_bfloat16* Bb[NB];
    Bb[0] = B0 + (size_t)(bx * 128) * K;
    if (NB > 1) Bb[1] = B1 + (size_t)(bx * 128) * K;
    if (NB > 2) Bb[2] = B2 + (size_t)(bx * 128) * K;

    const int lrow = tid >> 3;
    const int lcg  = (tid & 7) * 8;

    const uint32_t aoff = (uint32_t)((wm + (lane & 7) + ((lane >> 3) & 1) * 8) * ROWB
                                     + (lane >> 4) * 16);
    const uint32_t boff = (uint32_t)((wn + (lane & 7) + (lane >> 4) * 8) * ROWB
                                     + ((lane >> 3) & 1) * 16);

    float acc[4][4][4];
#pragma unroll
    for (int i = 0; i < 4; i++)
#pragma unroll
        for (int j = 0; j < 4; j++)
#pragma unroll
            for (int q = 0; q < 4; q++) acc[i][j][q] = 0.0f;

    const int nchunk = K >> 6;

    auto load_stage = [&](int c, int s) {
        const int k0 = c * 64;
        uint32_t base = sb + s * STAGEB;
#pragma unroll
        for (int i = 0; i < 4; i++) {
            int row = lrow + i * 32;
            uint32_t so = base + row * ROWB + lcg * 2;
            cp16(so, Ab + (size_t)row * K + k0 + lcg);
#pragma unroll
            for (int b = 0; b < NB; b++)
                cp16(so + (b + 1) * MATB, Bb[b] + (size_t)row * K + k0 + lcg);
        }
        cp_commit();
    };

    load_stage(0, 0);

    for (int c = 0; c < nchunk; c++) {
        if (c + 1 < nchunk) { load_stage(c + 1, (c + 1) & 1); cp_wait<1>(); }
        else                { cp_wait<0>(); }
        __syncthreads();

        const uint32_t abase = sb + (c & 1) * STAGEB + aoff;
        const uint32_t bbase = sb + (c & 1) * STAGEB + boff;

#pragma unroll
        for (int kk = 0; kk < 4; kk++) {
            uint32_t a[4][4];
#pragma unroll
            for (int mt = 0; mt < 4; mt++)
                ldsm4(a[mt], abase + mt * 16 * ROWB + kk * 32);
            uint32_t bf[NB][2][4];
#pragma unroll
            for (int b = 0; b < NB; b++)
#pragma unroll
                for (int np = 0; np < 2; np++)
                    ldsm4(bf[b][np], bbase + (b + 1) * MATB + np * 16 * ROWB + kk * 32);
#pragma unroll
            for (int nt = 0; nt < 4; nt++) {
#pragma unroll
                for (int b = 0; b < NB; b++) {
                    uint32_t b0 = bf[b][nt >> 1][(nt & 1) * 2];
                    uint32_t b1 = bf[b][nt >> 1][(nt & 1) * 2 + 1];
#pragma unroll
                    for (int mt = 0; mt < 4; mt++)
                        mma16816(acc[mt][nt], a[mt], b0, b1);
                }
            }
        }
        __syncthreads();
    }

#pragma unroll
    for (int mt = 0; mt < 4; mt++) {
#pragma unroll
        for (int nt = 0; nt < 4; nt++) {
            int row = by * 128 + wm + mt * 16 + g;
            int col = bx * 128 + wn + nt * 8 + tig * 2;
            float bv0 = bias[col], bv1 = bias[col + 1];
            if (DEC1) {
#pragma unroll
                for (int h = 0; h < 2; h++) {
                    float c0 = acc[mt][nt][2*h]   + bv0;
                    float c1 = acc[mt][nt][2*h+1] + bv1;
                    float m0 = 0.0f, m1 = 0.0f;
                    uint32_t* dst = reinterpret_cast<uint32_t*>(
                        S3 + (size_t)(row + h * 8) * 256 + col);
#pragma unroll
                    for (int j = 0; j < 8; j++) {
                        float r0 = (m0 - 1.0f > 0.0f) ? 1.0f : 0.0f;
                        float r1 = (m1 - 1.0f > 0.0f) ? 1.0f : 0.0f;
                        m0 = 0.9f * m0 + c0 - r0;
                        m1 = 0.9f * m1 + c1 - r1;
                        dst[j * 1048576] = spike_pack_h(m0, m1);
                    }
                }
            } else {
                float2 v0 = make_float2(acc[mt][nt][0] + bv0, acc[mt][nt][1] + bv1);
                float2 v1 = make_float2(acc[mt][nt][2] + bv0, acc[mt][nt][3] + bv1);
                *reinterpret_cast<float2*>(C + (size_t)row * N + col)       = v0;
                *reinterpret_cast<float2*>(C + (size_t)(row + 8) * N + col) = v1;
            }
        }
    }
}

// ===================== fused G4 (single fp16) + m4 scan + output ===========
// grid = (8, 64), block 256 (8 warps 4x2, warp 32x32).
// __launch_bounds__(256,3): occupancy 2->3 CTAs/SM (3 x 73728 B smem fits).

static const int F_SBB  = 9216;               // 64 rows * 144 B per K-64 chunk
static const int F_SBA  = 4 * F_SBB;          // 36864: W4 = 4 chunks
static const int F_SMEM = F_SBA + 2 * MATB;   // + A double stage = 73728

__global__ __launch_bounds__(256, 3) void gemm4_fused(
    const __half* __restrict__ A,             // s3 [65536, 256] fp16 spikes
    const __half* __restrict__ B0,            // w4h [512, 256] fp16
    const float* __restrict__ bias,
    float* __restrict__ out)                  // mem @0, spk @ +33554432
{
    extern __shared__ char sm[];
    const uint32_t sb = smem_u32(sm);
    const int tid = threadIdx.x, wid = tid >> 5, lane = tid & 31;
    const int bx = blockIdx.x, by = blockIdx.y;
    const int g = lane >> 2, tig = lane & 3;
    const int wm = (wid >> 1) * 32, wn = (wid & 1) * 32;

    {
        const __half* Bsrc = B0 + (size_t)(bx * 64) * 256;
#pragma unroll
        for (int i = 0; i < 8; i++) {
            int w = tid + i * 256;
            int row = w >> 5, kcg = (w & 31) * 8;
            uint32_t dst = sb + (uint32_t)((kcg >> 6) * F_SBB +
                                           row * ROWB + (kcg & 63) * 2);
            cp16(dst, Bsrc + (size_t)row * 256 + kcg);
        }
    }

    const int lrow = tid >> 3;
    const int lcg  = (tid & 7) * 8;
    auto load_stageA = [&](int gc) {
        int j = gc >> 2, kc = gc & 3;
        const __half* Ab = A + (size_t)(j * 8192 + by * 128) * 256 + kc * 64;
        uint32_t base = sb + (uint32_t)(F_SBA + (gc & 1) * MATB);
#pragma unroll
        for (int i = 0; i < 4; i++) {
            int row = lrow + i * 32;
            cp16(base + row * ROWB + lcg * 2, Ab + (size_t)row * 256 + lcg);
        }
        cp_commit();
    };

    load_stageA(0);

    const uint32_t aoff = (uint32_t)((wm + (lane & 7) + ((lane >> 3) & 1) * 8) * ROWB
                                     + (lane >> 4) * 16);
    const uint32_t boff = (uint32_t)((wn + (lane & 7) + (lane >> 4) * 8) * ROWB
                                     + ((lane >> 3) & 1) * 16);

    float bv[4][2];
#pragma unroll
    for (int nt = 0; nt < 4; nt++) {
        int col = bx * 64 + wn + nt * 8 + tig * 2;
        bv[nt][0] = bias[col]; bv[nt][1] = bias[col + 1];
    }

    float acc[2][4][4], m4[2][4][4];
#pragma unroll
    for (int i = 0; i < 2; i++)
#pragma unroll
        for (int j = 0; j < 4; j++)
#pragma unroll
            for (int q = 0; q < 4; q++) { acc[i][j][q] = 0.0f; m4[i][j][q] = 0.0f; }

    float* outspk = out + 33554432;
    const float4 zf4 = make_float4(0.f, 0.f, 0.f, 0.f);

    for (int gc = 0; gc < 32; gc++) {
        if (gc + 1 < 32) load_stageA(gc + 1);

#pragma unroll
        for (int p = 0; p < 2; p++) {
            int s = gc * 32 + p * 16 + (tid >> 4);       // 0..1023
            int jz = s >> 7, rz = s & 127;
            *reinterpret_cast<float4*>(
                outspk + ((size_t)(jz * 8192 + by * 128 + rz)) * 512
                       + bx * 64 + (tid & 15) * 4) = zf4;
        }

        if (gc + 1 < 32) cp_wait<1>(); else cp_wait<0>();
        __syncthreads();

        const uint32_t abase = sb + F_SBA + (gc & 1) * MATB + aoff;
        const int kc = gc & 3;

#pragma unroll
        for (int kk = 0; kk < 4; kk++) {
            uint32_t a[2][4];
#pragma unroll
            for (int mt = 0; mt < 2; mt++)
                ldsm4(a[mt], abase + mt * 16 * ROWB + kk * 32);
            uint32_t bf[2][4];
#pragma unroll
            for (int np = 0; np < 2; np++)
                ldsm4(bf[np], sb + kc * F_SBB + boff + np * 16 * ROWB + kk * 32);
#pragma unroll
            for (int nt = 0; nt < 4; nt++) {
                uint32_t b0 = bf[nt >> 1][(nt & 1) * 2];
                uint32_t b1 = bf[nt >> 1][(nt & 1) * 2 + 1];
                mma16816h(acc[0][nt], a[0], b0, b1);
                mma16816h(acc[1][nt], a[1], b0, b1);
            }
        }
        __syncthreads();

        if ((gc & 3) == 3) {
            const int j = gc >> 2;
#pragma unroll
            for (int mt = 0; mt < 2; mt++) {
#pragma unroll
                for (int nt = 0; nt < 4; nt++) {
                    int r0  = by * 128 + wm + mt * 16 + g;
                    int col = bx * 64 + wn + nt * 8 + tig * 2;
#pragma unroll
                    for (int h = 0; h < 2; h++) {
                        float c0 = acc[mt][nt][2*h]   + bv[nt][0];
                        float c1 = acc[mt][nt][2*h+1] + bv[nt][1];
                        float m0 = 0.9f * m4[mt][nt][2*h]   + c0;   // reset==0
                        float m1 = 0.9f * m4[mt][nt][2*h+1] + c1;
                        m4[mt][nt][2*h] = m0; m4[mt][nt][2*h+1] = m1;
                        size_t base = ((size_t)(j * 8192 + r0 + h * 8)) * 512 + col;
                        *reinterpret_cast<float2*>(out + base) = make_float2(m0, m1);
                        acc[mt][nt][2*h] = 0.0f; acc[mt][nt][2*h+1] = 0.0f;
                    }
                }
            }
        }
    }
}

// ===================== split + scan kernels ================================

__global__ void split_all(const float* __restrict__ W2, const float* __restrict__ W3,
                          const float* __restrict__ W4) {
    int b = blockIdx.x;
    if (b < 128) {
        int i = b * 256 + threadIdx.x;
        float w = W2[i];
        __nv_bfloat16 h = __float2bfloat16(w);
        float r1 = w - __bfloat162float(h);
        __nv_bfloat16 m = __float2bfloat16(r1);
        g_w2hi[i] = h; g_w2mi[i] = m;
        g_w2lo[i] = __float2bfloat16(r1 - __bfloat162float(m));
    } else if (b < 256) {
        int i = (b - 128) * 256 + threadIdx.x;
        float w = W3[i];
        __nv_bfloat16 h = __float2bfloat16(w);
        float r1 = w - __bfloat162float(h);
        __nv_bfloat16 m = __float2bfloat16(r1);
        g_w3hi[i] = h; g_w3mi[i] = m;
        g_w3lo[i] = __float2bfloat16(r1 - __bfloat162float(m));
    } else {
        int i = (b - 256) * 256 + threadIdx.x;
        g_w4h[i] = __float2half(W4[i]);
    }
}

__global__ void enc2_scan() {
    int t4 = (blockIdx.x * blockDim.x + threadIdx.x) * 4;   // < 131072
    float m0 = 0.0f, m1 = 0.0f, m2 = 0.0f, m3 = 0.0f;
#pragma unroll
    for (int k = 0; k < 8; k++) {
        float4 c = *reinterpret_cast<const float4*>(&g_cur2[k*131072 + t4]);
        float r0 = (m0 - 1.0f > 0.0f) ? 1.0f : 0.0f;
        float r1 = (m1 - 1.0f > 0.0f) ? 1.0f : 0.0f;
        float r2 = (m2 - 1.0f > 0.0f) ? 1.0f : 0.0f;
        float r3 = (m3 - 1.0f > 0.0f) ? 1.0f : 0.0f;
        m0 = 0.9f * m0 + c.x - r0;
        m1 = 0.9f * m1 + c.y - r1;
        m2 = 0.9f * m2 + c.z - r2;
        m3 = 0.9f * m3 + c.w - r3;
        uint2 sp;
        sp.x = spike_pack(m0, m1, 1.0f);
        sp.y = spike_pack(m2, m3, 1.0f);
        *reinterpret_cast<uint2*>(&g_spk[k*131072 + t4]) = sp;
    }
}

// ===================== launch ==============================================

extern "C" void kernel_launch(void* const* d_in, const int* in_sizes, int n_in,
                              void* d_out, int out_size) {
    const float* x  = (const float*)d_in[0];
    const float* W1 = (const float*)d_in[1];
    const float* b1 = (const float*)d_in[2];
    const float* W2 = (const float*)d_in[3];
    const float* b2 = (const float*)d_in[4];
    const float* W3 = (const float*)d_in[5];
    const float* b3 = (const float*)d_in[6];
    const float* W4 = (const float*)d_in[7];
    const float* b4 = (const float*)d_in[8];

    float *cur2;
    __nv_bfloat16 *s1, *spk;
    __half *s3, *w4h;
    __nv_bfloat16 *w2h, *w2m, *w2l, *w3h, *w3m, *w3l;
    cudaGetSymbolAddress((void**)&s1,   g_s1);
    cudaGetSymbolAddress((void**)&cur2, g_cur2);
    cudaGetSymbolAddress((void**)&spk,  g_spk);
    cudaGetSymbolAddress((void**)&s3,   g_s3);
    cudaGetSymbolAddress((void**)&w2h,  g_w2hi);
    cudaGetSymbolAddress((void**)&w2m,  g_w2mi);
    cudaGetSymbolAddress((void**)&w2l,  g_w2lo);
    cudaGetSymbolAddress((void**)&w3h,  g_w3hi);
    cudaGetSymbolAddress((void**)&w3m,  g_w3mi);
    cudaGetSymbolAddress((void**)&w3l,  g_w3lo);
    cudaGetSymbolAddress((void**)&w4h,  g_w4h);

    const int SMEM3 = 2 * 4 * MATB;   // 147456
    cudaFuncSetAttribute(mma_gemm_split<3,false>,
                         cudaFuncAttributeMaxDynamicSharedMemorySize, SMEM3);
    cudaFuncSetAttribute(mma_gemm_split<3,true>,
                         cudaFuncAttributeMaxDynamicSharedMemorySize, SMEM3);
    cudaFuncSetAttribute(gemm4_fused,
                         cudaFuncAttributeMaxDynamicSharedMemorySize, F_SMEM);

    split_all<<<768, 256>>>(W2, W3, W4);

    // G1 + enc1: s1 spikes directly from x @ W1^T + b1
    g1_enc1<<<dim3(8, 16), 256>>>(x, W1, b1, s1);

    // G2: cur2 = s1 @ W2^T + b2  [8192,128], K=256  (bf16 3-split)
    mma_gemm_split<3,false><<<dim3(1, 64), 256, SMEM3>>>(
        s1, w2h, w2m, w2l, b2, cur2, nullptr, 8192, 128, 256);
    enc2_scan<<<128, 256>>>();

    // G3 + dec1: s3 (fp16 spikes) from spk @ W3^T + b3  [8192,256], K=128
    mma_gemm_split<3,true><<<dim3(2, 64), 256, SMEM3>>>(
        spk, w3h, w3m, w3l, b3, nullptr, s3, 8192, 256, 128);

    // G4 (single fp16 HMMA) fused with m4 scan + mem stores + spk zero-fill
    gemm4_fused<<<dim3(8, 64), 256, F_SMEM>>>(s3, w4h, b4, (float*)d_out);
}

// round 15
// speedup vs baseline: 1.3024x; 1.3024x over previous
#include <cuda_runtime.h>
#include <cuda_bf16.h>
#include <cuda_fp16.h>
#include <cstdint>

// ---------------------------------------------------------------------------
// Net_9560597201379 : SNN encoder/decoder.  (round-11 structure)
//   G1+enc1 fused: fp32 scalar-FMA GEMM (exact sequential-k chain).
//   G2: HMMA bf16 3-way-split W -> cur2 ; enc2 scan standalone.
//   G3+dec1 fused: HMMA bf16 3-way-split W, m3 scan in regs -> s3 (fp16).
//   G4 fused: single-pass fp16 HMMA + m4 scan (reset provably 0) + spk
//     zero-fill.  NEW: 3-stage A pipeline with ONE __syncthreads per
//     k-group (was 2) -- barrier count halved, loads covered by a full
//     MMA iteration.  Registers/arithmetic identical to round 11.
// ---------------------------------------------------------------------------

__device__ __nv_bfloat16  g_s1  [8*1024*256];
__device__ float          g_cur2[8*1024*128];
__device__ __nv_bfloat16  g_spk [8*1024*128];
__device__ __half         g_s3  [8*8192*256];
__device__ __nv_bfloat16  g_w2hi[128*256], g_w2mi[128*256], g_w2lo[128*256];
__device__ __nv_bfloat16  g_w3hi[256*128], g_w3mi[256*128], g_w3lo[256*128];
__device__ __half         g_w4h [512*256];

// ===================== helpers =============================================

__device__ __forceinline__ uint32_t smem_u32(const void* p) {
    uint32_t a;
    asm("{ .reg .u64 t; cvta.to.shared.u64 t, %1; cvt.u32.u64 %0, t; }"
        : "=r"(a) : "l"(p));
    return a;
}

__device__ __forceinline__ void cp16(uint32_t s, const void* g) {
    asm volatile("cp.async.cg.shared.global [%0], [%1], 16;" :: "r"(s), "l"(g));
}
__device__ __forceinline__ void cp_commit() {
    asm volatile("cp.async.commit_group;");
}
template <int N> __device__ __forceinline__ void cp_wait() {
    asm volatile("cp.async.wait_group %0;" :: "n"(N));
}

__device__ __forceinline__ void mma16816(float* d, const uint32_t* a,
                                         uint32_t b0, uint32_t b1) {
    asm volatile(
        "mma.sync.aligned.m16n8k16.row.col.f32.bf16.bf16.f32 "
        "{%0,%1,%2,%3}, {%4,%5,%6,%7}, {%8,%9}, {%0,%1,%2,%3};"
        : "+f"(d[0]), "+f"(d[1]), "+f"(d[2]), "+f"(d[3])
        : "r"(a[0]), "r"(a[1]), "r"(a[2]), "r"(a[3]), "r"(b0), "r"(b1));
}

__device__ __forceinline__ void mma16816h(float* d, const uint32_t* a,
                                          uint32_t b0, uint32_t b1) {
    asm volatile(
        "mma.sync.aligned.m16n8k16.row.col.f32.f16.f16.f32 "
        "{%0,%1,%2,%3}, {%4,%5,%6,%7}, {%8,%9}, {%0,%1,%2,%3};"
        : "+f"(d[0]), "+f"(d[1]), "+f"(d[2]), "+f"(d[3])
        : "r"(a[0]), "r"(a[1]), "r"(a[2]), "r"(a[3]), "r"(b0), "r"(b1));
}

__device__ __forceinline__ void ldsm4(uint32_t* r, uint32_t a) {
    asm volatile("ldmatrix.sync.aligned.m8n8.x4.shared.b16 {%0,%1,%2,%3}, [%4];"
                 : "=r"(r[0]), "=r"(r[1]), "=r"(r[2]), "=r"(r[3]) : "r"(a));
}

// spike pair -> packed bf16x2 bits (1.0f bf16 = 0x3F80)
__device__ __forceinline__ uint32_t spike_pack(float m0, float m1, float th) {
    uint32_t lo = (m0 - th > 0.0f) ? 0x3F80u : 0u;
    uint32_t hi = (m1 - th > 0.0f) ? 0x3F80u : 0u;
    return lo | (hi << 16);
}
// spike pair -> packed fp16x2 bits (1.0f fp16 = 0x3C00)
__device__ __forceinline__ uint32_t spike_pack_h(float m0, float m1) {
    uint32_t lo = (m0 - 1.0f > 0.0f) ? 0x3C00u : 0u;
    uint32_t hi = (m1 - 1.0f > 0.0f) ? 0x3C00u : 0u;
    return lo | (hi << 16);
}

static const int ROWB = 144;              // smem row: 64 b16 data + pad
static const int MATB = 128 * ROWB;       // 18432 B per 128x64 tile

// ===================== G1 + enc1 fused =====================================
// grid = (8,16), block 256.  Exact chain: fma.rn ascending k, +bias last.

__global__ __launch_bounds__(256) void g1_enc1(
    const float* __restrict__ A, const float* __restrict__ B,
    const float* __restrict__ bias, __nv_bfloat16* __restrict__ S1)
{
    __shared__ float As[16][68];   // [k][row]
    __shared__ float Bs[16][36];   // [k][col]

    const int tid = threadIdx.x;
    const int bx = blockIdx.x, by = blockIdx.y;
    const int arow = tid >> 2, akq = (tid & 3) * 4;
    const int brow = tid >> 3, bkq = (tid & 7) * 2;
    const int tr = (tid >> 4) * 4, tc = (tid & 15) * 2;

    const float* Ab = A + (size_t)(by * 64) * 512;
    const float* Bb = B + (size_t)(bx * 32) * 512;

    float4 ar = *reinterpret_cast<const float4*>(Ab + arow * 512 + akq);
    float2 br = *reinterpret_cast<const float2*>(Bb + brow * 512 + bkq);

    float acc[4][2];
#pragma unroll
    for (int i = 0; i < 4; i++) { acc[i][0] = 0.0f; acc[i][1] = 0.0f; }

    for (int c = 0; c < 32; c++) {
        As[akq + 0][arow] = ar.x;
        As[akq + 1][arow] = ar.y;
        As[akq + 2][arow] = ar.z;
        As[akq + 3][arow] = ar.w;
        Bs[bkq + 0][brow] = br.x;
        Bs[bkq + 1][brow] = br.y;
        __syncthreads();
        if (c + 1 < 32) {
            ar = *reinterpret_cast<const float4*>(Ab + arow * 512 + (c + 1) * 16 + akq);
            br = *reinterpret_cast<const float2*>(Bb + brow * 512 + (c + 1) * 16 + bkq);
        }
#pragma unroll
        for (int kk = 0; kk < 16; kk++) {
            float4 av = *reinterpret_cast<const float4*>(&As[kk][tr]);
            float b0 = Bs[kk][tc], b1 = Bs[kk][tc + 1];
            acc[0][0] = fmaf(av.x, b0, acc[0][0]);
            acc[0][1] = fmaf(av.x, b1, acc[0][1]);
            acc[1][0] = fmaf(av.y, b0, acc[1][0]);
            acc[1][1] = fmaf(av.y, b1, acc[1][1]);
            acc[2][0] = fmaf(av.z, b0, acc[2][0]);
            acc[2][1] = fmaf(av.z, b1, acc[2][1]);
            acc[3][0] = fmaf(av.w, b0, acc[3][0]);
            acc[3][1] = fmaf(av.w, b1, acc[3][1]);
        }
        __syncthreads();
    }

    const int col = bx * 32 + tc;
    const float bv0 = bias[col], bv1 = bias[col + 1];
#pragma unroll
    for (int i = 0; i < 4; i++) {
        const int row = by * 64 + tr + i;
        float c0 = acc[i][0] + bv0;
        float c1 = acc[i][1] + bv1;
        float m0 = 0.0f, m1 = 0.0f;
        uint32_t* dst = reinterpret_cast<uint32_t*>(S1 + (size_t)row * 256 + col);
#pragma unroll
        for (int k = 0; k < 8; k++) {
            float r0 = (m0 - 1.0f > 0.0f) ? 1.0f : 0.0f;
            float r1 = (m1 - 1.0f > 0.0f) ? 1.0f : 0.0f;
            m0 = 0.9f * m0 + c0 - r0;
            m1 = 0.9f * m1 + c1 - r1;
            dst[k * 131072] = spike_pack(m0, m1, 1.0f);
        }
    }
}

// ===================== generic HMMA GEMM (G2 / G3+dec1) ====================
// bf16, 3-way-split weights; bitwise-identical to the proven round-8 version.

template <int NB, bool DEC1>
__global__ __launch_bounds__(256, 2) void mma_gemm_split(
    const __nv_bfloat16* __restrict__ A,
    const __nv_bfloat16* __restrict__ B0,
    const __nv_bfloat16* __restrict__ B1,
    const __nv_bfloat16* __restrict__ B2,
    const float* __restrict__ bias,
    float* __restrict__ C, __half* __restrict__ S3,
    int M, int N, int K)
{
    constexpr int STAGEB = (1 + NB) * MATB;
    extern __shared__ char sm[];
    const uint32_t sb = smem_u32(sm);
    const int tid = threadIdx.x, wid = tid >> 5, lane = tid & 31;
    const int bx = blockIdx.x, by = blockIdx.y;
    const int g = lane >> 2, tig = lane & 3;
    const int wm = (wid >> 2) * 64, wn = (wid & 3) * 32;

    const __nv_bfloat16* Ab = A + (size_t)(by * 128) * K;
    const __nv_bfloat16* Bb[NB];
    Bb[0] = B0 + (size_t)(bx * 128) * K;
    if (NB > 1) Bb[1] = B1 + (size_t)(bx * 128) * K;
    if (NB > 2) Bb[2] = B2 + (size_t)(bx * 128) * K;

    const int lrow = tid >> 3;
    const int lcg  = (tid & 7) * 8;

    const uint32_t aoff = (uint32_t)((wm + (lane & 7) + ((lane >> 3) & 1) * 8) * ROWB
                                     + (lane >> 4) * 16);
    const uint32_t boff = (uint32_t)((wn + (lane & 7) + (lane >> 4) * 8) * ROWB
                                     + ((lane >> 3) & 1) * 16);

    float acc[4][4][4];
#pragma unroll
    for (int i = 0; i < 4; i++)
#pragma unroll
        for (int j = 0; j < 4; j++)
#pragma unroll
            for (int q = 0; q < 4; q++) acc[i][j][q] = 0.0f;

    const int nchunk = K >> 6;

    auto load_stage = [&](int c, int s) {
        const int k0 = c * 64;
        uint32_t base = sb + s * STAGEB;
#pragma unroll
        for (int i = 0; i < 4; i++) {
            int row = lrow + i * 32;
            uint32_t so = base + row * ROWB + lcg * 2;
            cp16(so, Ab + (size_t)row * K + k0 + lcg);
#pragma unroll
            for (int b = 0; b < NB; b++)
                cp16(so + (b + 1) * MATB, Bb[b] + (size_t)row * K + k0 + lcg);
        }
        cp_commit();
    };

    load_stage(0, 0);

    for (int c = 0; c < nchunk; c++) {
        if (c + 1 < nchunk) { load_stage(c + 1, (c + 1) & 1); cp_wait<1>(); }
        else                { cp_wait<0>(); }
        __syncthreads();

        const uint32_t abase = sb + (c & 1) * STAGEB + aoff;
        const uint32_t bbase = sb + (c & 1) * STAGEB + boff;

#pragma unroll
        for (int kk = 0; kk < 4; kk++) {
            uint32_t a[4][4];
#pragma unroll
            for (int mt = 0; mt < 4; mt++)
                ldsm4(a[mt], abase + mt * 16 * ROWB + kk * 32);
            uint32_t bf[NB][2][4];
#pragma unroll
            for (int b = 0; b < NB; b++)
#pragma unroll
                for (int np = 0; np < 2; np++)
                    ldsm4(bf[b][np], bbase + (b + 1) * MATB + np * 16 * ROWB + kk * 32);
#pragma unroll
            for (int nt = 0; nt < 4; nt++) {
#pragma unroll
                for (int b = 0; b < NB; b++) {
                    uint32_t b0 = bf[b][nt >> 1][(nt & 1) * 2];
                    uint32_t b1 = bf[b][nt >> 1][(nt & 1) * 2 + 1];
#pragma unroll
                    for (int mt = 0; mt < 4; mt++)
                        mma16816(acc[mt][nt], a[mt], b0, b1);
                }
            }
        }
        __syncthreads();
    }

#pragma unroll
    for (int mt = 0; mt < 4; mt++) {
#pragma unroll
        for (int nt = 0; nt < 4; nt++) {
            int row = by * 128 + wm + mt * 16 + g;
            int col = bx * 128 + wn + nt * 8 + tig * 2;
            float bv0 = bias[col], bv1 = bias[col + 1];
            if (DEC1) {
#pragma unroll
                for (int h = 0; h < 2; h++) {
                    float c0 = acc[mt][nt][2*h]   + bv0;
                    float c1 = acc[mt][nt][2*h+1] + bv1;
                    float m0 = 0.0f, m1 = 0.0f;
                    uint32_t* dst = reinterpret_cast<uint32_t*>(
                        S3 + (size_t)(row + h * 8) * 256 + col);
#pragma unroll
                    for (int j = 0; j < 8; j++) {
                        float r0 = (m0 - 1.0f > 0.0f) ? 1.0f : 0.0f;
                        float r1 = (m1 - 1.0f > 0.0f) ? 1.0f : 0.0f;
                        m0 = 0.9f * m0 + c0 - r0;
                        m1 = 0.9f * m1 + c1 - r1;
                        dst[j * 1048576] = spike_pack_h(m0, m1);
                    }
                }
            } else {
                float2 v0 = make_float2(acc[mt][nt][0] + bv0, acc[mt][nt][1] + bv1);
                float2 v1 = make_float2(acc[mt][nt][2] + bv0, acc[mt][nt][3] + bv1);
                *reinterpret_cast<float2*>(C + (size_t)row * N + col)       = v0;
                *reinterpret_cast<float2*>(C + (size_t)(row + 8) * N + col) = v1;
            }
        }
    }
}

// ===================== fused G4 (single fp16) + m4 scan + output ===========
// grid = (8, 64), block 256 (8 warps 4x2, warp 32x32).
// 3-stage A pipeline, ONE __syncthreads per k-group: stage gc+2's load is
// issued right after the barrier (its buffer was last read at gc-1, fenced
// by this barrier).  Epilogue reads registers only -> no second barrier.

static const int F_SBB  = 9216;               // 64 rows * 144 B per K-64 chunk
static const int F_SBA  = 4 * F_SBB;          // 36864: W4 = 4 chunks
static const int F_SMEM = F_SBA + 3 * MATB;   // + A triple stage = 92160

__global__ __launch_bounds__(256, 2) void gemm4_fused(
    const __half* __restrict__ A,             // s3 [65536, 256] fp16 spikes
    const __half* __restrict__ B0,            // w4h [512, 256] fp16
    const float* __restrict__ bias,
    float* __restrict__ out)                  // mem @0, spk @ +33554432
{
    extern __shared__ char sm[];
    const uint32_t sb = smem_u32(sm);
    const int tid = threadIdx.x, wid = tid >> 5, lane = tid & 31;
    const int bx = blockIdx.x, by = blockIdx.y;
    const int g = lane >> 2, tig = lane & 3;
    const int wm = (wid >> 1) * 32, wn = (wid & 1) * 32;

    // resident B: 64 rows x 256 fp16 -> 4 chunk tiles (part of cp group 0)
    {
        const __half* Bsrc = B0 + (size_t)(bx * 64) * 256;
#pragma unroll
        for (int i = 0; i < 8; i++) {
            int w = tid + i * 256;
            int row = w >> 5, kcg = (w & 31) * 8;
            uint32_t dst = sb + (uint32_t)((kcg >> 6) * F_SBB +
                                           row * ROWB + (kcg & 63) * 2);
            cp16(dst, Bsrc + (size_t)row * 256 + kcg);
        }
    }

    const int lrow = tid >> 3;
    const int lcg  = (tid & 7) * 8;
    auto load_stageA = [&](int gc) {
        int j = gc >> 2, kc = gc & 3;
        const __half* Ab = A + (size_t)(j * 8192 + by * 128) * 256 + kc * 64;
        int st = gc % 3;
        uint32_t base = sb + (uint32_t)(F_SBA + st * MATB);
#pragma unroll
        for (int i = 0; i < 4; i++) {
            int row = lrow + i * 32;
            cp16(base + row * ROWB + lcg * 2, Ab + (size_t)row * 256 + lcg);
        }
        cp_commit();
    };

    load_stageA(0);   // group 0 = {B + A0}
    load_stageA(1);   // group 1 = A1

    const uint32_t aoff = (uint32_t)((wm + (lane & 7) + ((lane >> 3) & 1) * 8) * ROWB
                                     + (lane >> 4) * 16);
    const uint32_t boff = (uint32_t)((wn + (lane & 7) + (lane >> 4) * 8) * ROWB
                                     + ((lane >> 3) & 1) * 16);

    float bv[4][2];
#pragma unroll
    for (int nt = 0; nt < 4; nt++) {
        int col = bx * 64 + wn + nt * 8 + tig * 2;
        bv[nt][0] = bias[col]; bv[nt][1] = bias[col + 1];
    }

    float acc[2][4][4], m4[2][4][4];
#pragma unroll
    for (int i = 0; i < 2; i++)
#pragma unroll
        for (int j = 0; j < 4; j++)
#pragma unroll
            for (int q = 0; q < 4; q++) { acc[i][j][q] = 0.0f; m4[i][j][q] = 0.0f; }

    float* outspk = out + 33554432;
    const float4 zf4 = make_float4(0.f, 0.f, 0.f, 0.f);

    for (int gc = 0; gc < 32; gc++) {
        // stage gc ready when <=1 younger group outstanding
        if (gc + 1 < 32) cp_wait<1>(); else cp_wait<0>();
        __syncthreads();

        // issue load for gc+2 (buffer (gc+2)%3 was last read at gc-1, fenced)
        if (gc + 2 < 32) load_stageA(gc + 2);

        // spread spk zero-fill (pure gmem stores, overlap with MMA below)
#pragma unroll
        for (int p = 0; p < 2; p++) {
            int s = gc * 32 + p * 16 + (tid >> 4);       // 0..1023
            int jz = s >> 7, rz = s & 127;
            *reinterpret_cast<float4*>(
                outspk + ((size_t)(jz * 8192 + by * 128 + rz)) * 512
                       + bx * 64 + (tid & 15) * 4) = zf4;
        }

        const uint32_t abase = sb + F_SBA + (gc % 3) * MATB + aoff;
        const int kc = gc & 3;

#pragma unroll
        for (int kk = 0; kk < 4; kk++) {
            uint32_t a[2][4];
#pragma unroll
            for (int mt = 0; mt < 2; mt++)
                ldsm4(a[mt], abase + mt * 16 * ROWB + kk * 32);
            uint32_t bf[2][4];
#pragma unroll
            for (int np = 0; np < 2; np++)
                ldsm4(bf[np], sb + kc * F_SBB + boff + np * 16 * ROWB + kk * 32);
#pragma unroll
            for (int nt = 0; nt < 4; nt++) {
                uint32_t b0 = bf[nt >> 1][(nt & 1) * 2];
                uint32_t b1 = bf[nt >> 1][(nt & 1) * 2 + 1];
                mma16816h(acc[0][nt], a[0], b0, b1);
                mma16816h(acc[1][nt], a[1], b0, b1);
            }
        }

        if ((gc & 3) == 3) {
            const int j = gc >> 2;
#pragma unroll
            for (int mt = 0; mt < 2; mt++) {
#pragma unroll
                for (int nt = 0; nt < 4; nt++) {
                    int r0  = by * 128 + wm + mt * 16 + g;
                    int col = bx * 64 + wn + nt * 8 + tig * 2;
#pragma unroll
                    for (int h = 0; h < 2; h++) {
                        float c0 = acc[mt][nt][2*h]   + bv[nt][0];
                        float c1 = acc[mt][nt][2*h+1] + bv[nt][1];
                        float m0 = 0.9f * m4[mt][nt][2*h]   + c0;   // reset==0
                        float m1 = 0.9f * m4[mt][nt][2*h+1] + c1;
                        m4[mt][nt][2*h] = m0; m4[mt][nt][2*h+1] = m1;
                        size_t base = ((size_t)(j * 8192 + r0 + h * 8)) * 512 + col;
                        *reinterpret_cast<float2*>(out + base) = make_float2(m0, m1);
                        acc[mt][nt][2*h] = 0.0f; acc[mt][nt][2*h+1] = 0.0f;
                    }
                }
            }
        }
    }
}

// ===================== split + scan kernels ================================

__global__ void split_all(const float* __restrict__ W2, const float* __restrict__ W3,
                          const float* __restrict__ W4) {
    int b = blockIdx.x;
    if (b < 128) {
        int i = b * 256 + threadIdx.x;
        float w = W2[i];
        __nv_bfloat16 h = __float2bfloat16(w);
        float r1 = w - __bfloat162float(h);
        __nv_bfloat16 m = __float2bfloat16(r1);
        g_w2hi[i] = h; g_w2mi[i] = m;
        g_w2lo[i] = __float2bfloat16(r1 - __bfloat162float(m));
    } else if (b < 256) {
        int i = (b - 128) * 256 + threadIdx.x;
        float w = W3[i];
        __nv_bfloat16 h = __float2bfloat16(w);
        float r1 = w - __bfloat162float(h);
        __nv_bfloat16 m = __float2bfloat16(r1);
        g_w3hi[i] = h; g_w3mi[i] = m;
        g_w3lo[i] = __float2bfloat16(r1 - __bfloat162float(m));
    } else {
        int i = (b - 256) * 256 + threadIdx.x;
        g_w4h[i] = __float2half(W4[i]);
    }
}

__global__ void enc2_scan() {
    int t4 = (blockIdx.x * blockDim.x + threadIdx.x) * 4;   // < 131072
    float m0 = 0.0f, m1 = 0.0f, m2 = 0.0f, m3 = 0.0f;
#pragma unroll
    for (int k = 0; k < 8; k++) {
        float4 c = *reinterpret_cast<const float4*>(&g_cur2[k*131072 + t4]);
        float r0 = (m0 - 1.0f > 0.0f) ? 1.0f : 0.0f;
        float r1 = (m1 - 1.0f > 0.0f) ? 1.0f : 0.0f;
        float r2 = (m2 - 1.0f > 0.0f) ? 1.0f : 0.0f;
        float r3 = (m3 - 1.0f > 0.0f) ? 1.0f : 0.0f;
        m0 = 0.9f * m0 + c.x - r0;
        m1 = 0.9f * m1 + c.y - r1;
        m2 = 0.9f * m2 + c.z - r2;
        m3 = 0.9f * m3 + c.w - r3;
        uint2 sp;
        sp.x = spike_pack(m0, m1, 1.0f);
        sp.y = spike_pack(m2, m3, 1.0f);
        *reinterpret_cast<uint2*>(&g_spk[k*131072 + t4]) = sp;
    }
}

// ===================== launch ==============================================

extern "C" void kernel_launch(void* const* d_in, const int* in_sizes, int n_in,
                              void* d_out, int out_size) {
    const float* x  = (const float*)d_in[0];
    const float* W1 = (const float*)d_in[1];
    const float* b1 = (const float*)d_in[2];
    const float* W2 = (const float*)d_in[3];
    const float* b2 = (const float*)d_in[4];
    const float* W3 = (const float*)d_in[5];
    const float* b3 = (const float*)d_in[6];
    const float* W4 = (const float*)d_in[7];
    const float* b4 = (const float*)d_in[8];

    float *cur2;
    __nv_bfloat16 *s1, *spk;
    __half *s3, *w4h;
    __nv_bfloat16 *w2h, *w2m, *w2l, *w3h, *w3m, *w3l;
    cudaGetSymbolAddress((void**)&s1,   g_s1);
    cudaGetSymbolAddress((void**)&cur2, g_cur2);
    cudaGetSymbolAddress((void**)&spk,  g_spk);
    cudaGetSymbolAddress((void**)&s3,   g_s3);
    cudaGetSymbolAddress((void**)&w2h,  g_w2hi);
    cudaGetSymbolAddress((void**)&w2m,  g_w2mi);
    cudaGetSymbolAddress((void**)&w2l,  g_w2lo);
    cudaGetSymbolAddress((void**)&w3h,  g_w3hi);
    cudaGetSymbolAddress((void**)&w3m,  g_w3mi);
    cudaGetSymbolAddress((void**)&w3l,  g_w3lo);
    cudaGetSymbolAddress((void**)&w4h,  g_w4h);

    const int SMEM3 = 2 * 4 * MATB;   // 147456
    cudaFuncSetAttribute(mma_gemm_split<3,false>,
                         cudaFuncAttributeMaxDynamicSharedMemorySize, SMEM3);
    cudaFuncSetAttribute(mma_gemm_split<3,true>,
                         cudaFuncAttributeMaxDynamicSharedMemorySize, SMEM3);
    cudaFuncSetAttribute(gemm4_fused,
                         cudaFuncAttributeMaxDynamicSharedMemorySize, F_SMEM);

    split_all<<<768, 256>>>(W2, W3, W4);

    // G1 + enc1: s1 spikes directly from x @ W1^T + b1
    g1_enc1<<<dim3(8, 16), 256>>>(x, W1, b1, s1);

    // G2: cur2 = s1 @ W2^T + b2  [8192,128], K=256  (bf16 3-split)
    mma_gemm_split<3,false><<<dim3(1, 64), 256, SMEM3>>>(
        s1, w2h, w2m, w2l, b2, cur2, nullptr, 8192, 128, 256);
    enc2_scan<<<128, 256>>>();

    // G3 + dec1: s3 (fp16 spikes) from spk @ W3^T + b3  [8192,256], K=128
    mma_gemm_split<3,true><<<dim3(2, 64), 256, SMEM3>>>(
        spk, w3h, w3m, w3l, b3, nullptr, s3, 8192, 256, 128);

    // G4 (single fp16 HMMA) fused with m4 scan + mem stores + spk zero-fill
    gemm4_fused<<<dim3(8, 64), 256, F_SMEM>>>(s3, w4h, b4, (float*)d_out);
}